// round 15
// baseline (speedup 1.0000x reference)
#include <cuda_runtime.h>
#include <cuda_fp16.h>
#include <math.h>

#define MREL 8
#define DDIM 256
#define MAXN 51200

typedef unsigned int u32;

// ---------------- scratch (no cudaMalloc allowed) ----------------
__device__ __half g_zsh[(size_t)MREL * MAXN * DDIM]; // fp16 copy of zs
__device__ float g_zsum[(size_t)MAXN * DDIM];        // fp32 (precision-critical)
__device__ __half g_zmaxh[(size_t)MAXN * DDIM];      // fp16
__device__ __half g_zagrh[(size_t)MAXN * DDIM];      // fp16
__device__ float g_zpre[(size_t)MAXN * DDIM];        // fp32
__device__ float g_logits[(size_t)MAXN * MREL];      // fp32
__device__ __half g_wTh[16 * 256 * 256];             // [m*2+mat][e][k] K-major fp16
__device__ __half g_wcTh[256 * 768];                 // [e][k] K-major fp16
__device__ __half g_wbTh[8 * 2048];                  // [j][k] K-major fp16

__device__ __forceinline__ u32 h2u(__half2 h) { return *(u32*)&h; }

// m16n8k16 fp16 mma, fp32 accum
__device__ __forceinline__ void mma16h(float* d, const u32* a, const u32* b) {
    asm volatile(
        "mma.sync.aligned.m16n8k16.row.col.f32.f16.f16.f32 "
        "{%0,%1,%2,%3}, {%4,%5,%6,%7}, {%8,%9}, {%0,%1,%2,%3};"
        : "+f"(d[0]), "+f"(d[1]), "+f"(d[2]), "+f"(d[3])
        : "r"(a[0]), "r"(a[1]), "r"(a[2]), "r"(a[3]), "r"(b[0]), "r"(b[1]));
}
__device__ __forceinline__ void cpa16(u32 dst, const void* src) {
    asm volatile("cp.async.cg.shared.global [%0], [%1], 16;" :: "r"(dst), "l"(src));
}
#define CP_COMMIT()   asm volatile("cp.async.commit_group;")
#define CP_WAIT1()    asm volatile("cp.async.wait_group 1;")
#define CP_WAITALL()  asm volatile("cp.async.wait_group 0;")

// hi/lo fp16 split of a float pair -> two packed b32
__device__ __forceinline__ void split2(float x, float y, u32& hi, u32& lo) {
    __half2 h = __floats2half2_rn(x, y);
    hi = h2u(h);
    __half2 l = __floats2half2_rn(x - __low2float(h), y - __high2float(h));
    lo = h2u(l);
}

// ============================================================================
// zs fp32 -> fp16 copy
// ============================================================================
__global__ void k_cvt_zs(const float* __restrict__ zs, long long n4) {
    long long i = blockIdx.x * (long long)blockDim.x + threadIdx.x;
    long long stride = (long long)gridDim.x * blockDim.x;
    for (; i < n4; i += stride) {
        float4 v = ((const float4*)zs)[i];
        __half2 h0 = __floats2half2_rn(v.x, v.y);
        __half2 h1 = __floats2half2_rn(v.z, v.w);
        ((uint2*)g_zsh)[i] = make_uint2(h2u(h0), h2u(h1));
    }
}

// ============================================================================
// Weight transposes (fp16 outputs, K-major)
// ============================================================================
__global__ void k_wtrans(const float* __restrict__ Wmax, const float* __restrict__ Wphi) {
    __shared__ float t[32][33];
    int z = blockIdx.z;
    const float* src = ((z & 1) ? Wphi : Wmax) + (size_t)(z >> 1) * 65536;
    __half* dst = g_wTh + (size_t)z * 65536;
    int e0 = blockIdx.x * 32, k0 = blockIdx.y * 32;
    int tx = threadIdx.x & 31, ty = threadIdx.x >> 5;
#pragma unroll
    for (int i = 0; i < 4; i++) t[ty + i * 8][tx] = src[(size_t)(k0 + ty + i * 8) * 256 + e0 + tx];
    __syncthreads();
#pragma unroll
    for (int i = 0; i < 4; i++)
        dst[(size_t)(e0 + ty + i * 8) * 256 + k0 + tx] = __float2half_rn(t[tx][ty + i * 8]);
}
__global__ void k_wctrans(const float* __restrict__ Wc) {
    __shared__ float t[32][33];
    int k0 = blockIdx.x * 32, e0 = blockIdx.y * 32;
    int tx = threadIdx.x & 31, ty = threadIdx.x >> 5;
#pragma unroll
    for (int i = 0; i < 4; i++) t[ty + i * 8][tx] = Wc[(size_t)(k0 + ty + i * 8) * 256 + e0 + tx];
    __syncthreads();
#pragma unroll
    for (int i = 0; i < 4; i++)
        g_wcTh[(size_t)(e0 + ty + i * 8) * 768 + k0 + tx] = __float2half_rn(t[tx][ty + i * 8]);
}
__global__ void k_wbtrans(const float* __restrict__ Wb) {
    int k = blockIdx.x * 256 + threadIdx.x;
    if (k < 2048) {
#pragma unroll
        for (int j = 0; j < 8; j++)
            g_wbTh[j * 2048 + k] = __float2half_rn(Wb[k * 8 + j]);
    }
}

// ============================================================================
// Kernel 1a: gate logits GEMM (fp16 mma, A hi/lo split in-register).
// ============================================================================
__global__ void __launch_bounds__(256, 2) k_gate_logits(
        const float* __restrict__ zs, const float* __restrict__ bb, int N) {
    extern __shared__ float sh[];
    u32 shb = (u32)__cvta_generic_to_shared(sh);
    float* sAf = sh;                                  // 2 x [128][68] fp32
    const u32 A0 = shb, B0 = shb + 2 * 34816;
    const u32* Bw = (const u32*)((const char*)sh + 2 * 34816);

    int tid = threadIdx.x, wid = tid >> 5, lane = tid & 31;
    int g = lane >> 2, t4 = lane & 3;
    int n0 = blockIdx.x * 128;

    auto stage = [&](int c) {
        int m = c >> 2, kc = (c & 3) * 64, s = c & 1;
        const float* za = zs + (size_t)m * N * DDIM;
        u32 sa = A0 + s * 34816, sb = B0 + s * 1152;
#pragma unroll
        for (int j = 0; j < 8; j++) {
            int f = tid + j * 256;
            int row = f >> 4, kq = f & 15;
            int nr = n0 + row; if (nr >= N) nr = N - 1;
            cpa16(sa + row * 272 + kq * 16, za + (size_t)nr * DDIM + kc + kq * 4);
        }
        if (tid < 64) {
            int row = tid >> 3, kq = tid & 7;
            cpa16(sb + row * 144 + kq * 16, g_wbTh + (size_t)row * 2048 + c * 64 + kq * 8);
        }
    };

    stage(0); CP_COMMIT();

    float d[4] = {0.f, 0.f, 0.f, 0.f};

    for (int c = 0; c < 32; c++) {
        int s = c & 1;
        CP_WAITALL();
        __syncthreads();
        if (c + 1 < 32) { stage(c + 1); CP_COMMIT(); }

        const float* A = sAf + s * 8704 + (wid * 16 + g) * 68;
        const u32* B = Bw + s * 288 + g * 36;
#pragma unroll
        for (int ks = 0; ks < 4; ks++) {
            int kf = ks * 16 + 2 * t4;
            float2 p0 = *(const float2*)(A + kf);
            float2 p1 = *(const float2*)(A + 8 * 68 + kf);
            float2 p2 = *(const float2*)(A + kf + 8);
            float2 p3 = *(const float2*)(A + 8 * 68 + kf + 8);
            u32 ahi[4], alo[4], b[2];
            split2(p0.x, p0.y, ahi[0], alo[0]);
            split2(p1.x, p1.y, ahi[1], alo[1]);
            split2(p2.x, p2.y, ahi[2], alo[2]);
            split2(p3.x, p3.y, ahi[3], alo[3]);
            b[0] = B[ks * 8 + t4];
            b[1] = B[ks * 8 + t4 + 4];
            mma16h(d, alo, b);
            mma16h(d, ahi, b);
        }
    }

    float bb0 = __ldg(bb + t4 * 2), bb1 = __ldg(bb + t4 * 2 + 1);
#pragma unroll
    for (int h = 0; h < 2; h++) {
        int n = n0 + wid * 16 + g + h * 8;
        if (n < N)
            *(float2*)(g_logits + (size_t)n * 8 + t4 * 2) =
                make_float2(d[h * 2] + bb0, d[h * 2 + 1] + bb1);
    }
}

// ============================================================================
// Kernel 1b: streaming softmax + z_sum (fp32 zs, exact). One warp per node.
// ============================================================================
__global__ void k_gate_zsum2(const float* __restrict__ zs, int N) {
    int tid = threadIdx.x;
    int lane = tid & 31, wid = tid >> 5;
    int n = blockIdx.x * 8 + wid;
    if (n >= N) return;

    const float* L = g_logits + (size_t)n * 8;
    float lg[8];
#pragma unroll
    for (int j = 0; j < 8; j++) lg[j] = __ldg(L + j);
    float mx = -1e30f;
#pragma unroll
    for (int j = 0; j < 8; j++) mx = fmaxf(mx, lg[j]);
    float gsm[8], se = 0.f;
#pragma unroll
    for (int j = 0; j < 8; j++) { gsm[j] = expf(lg[j] - mx); se += gsm[j]; }
    float inv = 1.f / se;
#pragma unroll
    for (int j = 0; j < 8; j++) gsm[j] *= inv;

    const float* base = zs + (size_t)n * DDIM + lane;
    float* q = g_zsum + (size_t)n * DDIM + lane;
    size_t mstr = (size_t)N * DDIM;
#pragma unroll
    for (int i = 0; i < 8; i++) {
        float v[8];
#pragma unroll
        for (int m = 0; m < 8; m++) v[m] = __ldg(base + m * mstr + 32 * i);
        float a = 0.f;
#pragma unroll
        for (int m = 0; m < 8; m++) a = fmaf(gsm[m], v[m], a);
        q[32 * i] = a;
    }
}

// ============================================================================
// Kernel 2: fused dual-GEMM + fold, fp16 m16n8k16. fp16 z_max / z_agr out.
// CTA 128 x 64, K-chunk 64, 3-stage cp.async distance 2.
// ============================================================================
__global__ void __launch_bounds__(256, 1) k_maxphi_mma(
        const float* __restrict__ bmax, const float* __restrict__ bphi, int N) {
    extern __shared__ float sh[];
    u32 shb = (u32)__cvta_generic_to_shared(sh);
    float* sbm = sh;                    // [8][64]
    float* sbp = sh + 512;              // [8][64]
    const u32 A0 = shb + 4096, B0 = shb + 4096 + 3 * 18432;
    const u32* Aw = (const u32*)((const char*)sh + 4096);
    const u32* Bw = (const u32*)((const char*)sh + 4096 + 3 * 18432);

    int tid = threadIdx.x, wid = tid >> 5, lane = tid & 31;
    int g = lane >> 2, t4 = lane & 3;
    int warpM = wid & 3, warpN = wid >> 2;
    int e0 = blockIdx.x * 64, n0 = blockIdx.y * 128;

    for (int i = tid; i < MREL * 64; i += 256) {
        int m = i >> 6, c = i & 63;
        sbm[i] = bmax[m * DDIM + e0 + c];
        sbp[i] = bphi[m * DDIM + e0 + c];
    }

    auto stage = [&](int it) {
        int m = it >> 2, k0 = (it & 3) * 64, s = it % 3;
        const __half* za = g_zsh + (size_t)m * N * DDIM;
        const __half* wb = g_wTh + (size_t)m * 2 * 65536;
        u32 sa = A0 + s * 18432, sb = B0 + s * 18432;
#pragma unroll
        for (int j = 0; j < 4; j++) {
            int f = tid + j * 256;
            int row = f >> 3, kq = f & 7;
            int nr = n0 + row; if (nr >= N) nr = N - 1;
            cpa16(sa + row * 144 + kq * 16, za + (size_t)nr * DDIM + k0 + kq * 8);
        }
#pragma unroll
        for (int j = 0; j < 4; j++) {
            int f = tid + j * 256;
            int row = f >> 3, kq = f & 7;
            const __half* src = wb + (row >= 64 ? 65536 : 0)
                                + (size_t)(e0 + (row & 63)) * 256 + k0 + kq * 8;
            cpa16(sb + row * 144 + kq * 16, src);
        }
    };

    stage(0); CP_COMMIT();
    stage(1); CP_COMMIT();

    float stP[32], stF1[32], stF2[32];
#pragma unroll
    for (int i = 0; i < 32; i++) { stP[i] = -3.0e38f; stF1[i] = 0.f; stF2[i] = 0.f; }

    float dP[2][4][4], dF[2][4][4];

    for (int it = 0; it < 32; it++) {
        int m = it >> 2, chunk = it & 3, s = it % 3;
        if (chunk == 0) {
#pragma unroll
            for (int mm = 0; mm < 2; mm++)
#pragma unroll
                for (int nn = 0; nn < 4; nn++)
#pragma unroll
                    for (int i = 0; i < 4; i++) { dP[mm][nn][i] = 0.f; dF[mm][nn][i] = 0.f; }
        }
        CP_WAIT1();
        __syncthreads();
        if (it + 2 < 32) { stage(it + 2); CP_COMMIT(); }

        int abase = s * 4608 + (warpM * 32 + g) * 36;
        int bbase = s * 4608 + (warpN * 32 + g) * 36;
#pragma unroll
        for (int ks = 0; ks < 4; ks++) {
            int ko = ks * 8 + t4;
            u32 a[2][4], bp[4][2], bf[4][2];
#pragma unroll
            for (int mm = 0; mm < 2; mm++) {
                int ab = abase + mm * 16 * 36 + ko;
                a[mm][0] = Aw[ab];
                a[mm][1] = Aw[ab + 8 * 36];
                a[mm][2] = Aw[ab + 4];
                a[mm][3] = Aw[ab + 8 * 36 + 4];
            }
#pragma unroll
            for (int nn = 0; nn < 4; nn++) {
                int bb_ = bbase + nn * 8 * 36 + ko;
                bp[nn][0] = Bw[bb_];           bp[nn][1] = Bw[bb_ + 4];
                bf[nn][0] = Bw[bb_ + 64 * 36]; bf[nn][1] = Bw[bb_ + 64 * 36 + 4];
            }
#pragma unroll
            for (int mm = 0; mm < 2; mm++)
#pragma unroll
                for (int nn = 0; nn < 4; nn++) {
                    mma16h(dP[mm][nn], a[mm], bp[nn]);
                    mma16h(dF[mm][nn], a[mm], bf[nn]);
                }
        }

        if (chunk == 3) {
#pragma unroll
            for (int nn = 0; nn < 4; nn++) {
                int cb = m * 64 + warpN * 32 + nn * 8 + t4 * 2;
                float bm0 = sbm[cb], bm1 = sbm[cb + 1];
                float bp0 = sbp[cb], bp1 = sbp[cb + 1];
#pragma unroll
                for (int mm = 0; mm < 2; mm++) {
                    int ix = mm * 16 + nn * 4;
                    stP[ix + 0] = fmaxf(stP[ix + 0], dP[mm][nn][0] + bm0);
                    stP[ix + 1] = fmaxf(stP[ix + 1], dP[mm][nn][1] + bm1);
                    stP[ix + 2] = fmaxf(stP[ix + 2], dP[mm][nn][2] + bm0);
                    stP[ix + 3] = fmaxf(stP[ix + 3], dP[mm][nn][3] + bm1);
                    float v0 = dF[mm][nn][0] + bp0, v1 = dF[mm][nn][1] + bp1;
                    float v2 = dF[mm][nn][2] + bp0, v3 = dF[mm][nn][3] + bp1;
                    stF1[ix + 0] += v0; stF2[ix + 0] = fmaf(v0, v0, stF2[ix + 0]);
                    stF1[ix + 1] += v1; stF2[ix + 1] = fmaf(v1, v1, stF2[ix + 1]);
                    stF1[ix + 2] += v2; stF2[ix + 2] = fmaf(v2, v2, stF2[ix + 2]);
                    stF1[ix + 3] += v3; stF2[ix + 3] = fmaf(v3, v3, stF2[ix + 3]);
                }
            }
        }
    }

#pragma unroll
    for (int mm = 0; mm < 2; mm++) {
#pragma unroll
        for (int h = 0; h < 2; h++) {
            int n = n0 + warpM * 32 + mm * 16 + g + h * 8;
            if (n >= N) continue;
#pragma unroll
            for (int nn = 0; nn < 4; nn++) {
                int ix = mm * 16 + nn * 4 + h * 2;
                int e = e0 + warpN * 32 + nn * 8 + t4 * 2;
                *(u32*)(g_zmaxh + (size_t)n * DDIM + e) =
                    h2u(__floats2half2_rn(stP[ix], stP[ix + 1]));
                float a0 = 0.5f * (stF1[ix] * stF1[ix] - stF2[ix]);
                float a1 = 0.5f * (stF1[ix + 1] * stF1[ix + 1] - stF2[ix + 1]);
                *(u32*)(g_zagrh + (size_t)n * DDIM + e) =
                    h2u(__floats2half2_rn(a0, a1));
            }
        }
    }
}

// ============================================================================
// Kernel 3a: combine part B — K chunks 4..12 (z_max fp16, z_agr fp16),
// single fp16 mma. Writes raw partials to g_zpre.
// smem: A fp16 2 x 18432 | B fp16 2 x 9216 = 55296 B -> 2 CTAs/SM.
// ============================================================================
__global__ void __launch_bounds__(256, 2) k_combine_b(int N) {
    extern __shared__ float sh[];
    u32 shb = (u32)__cvta_generic_to_shared(sh);
    const u32 A0 = shb, B0 = shb + 2 * 18432;
    const u32* Aw = (const u32*)sh;
    const u32* Bw = (const u32*)((const char*)sh + 2 * 18432);

    int tid = threadIdx.x, wid = tid >> 5, lane = tid & 31;
    int g = lane >> 2, t4 = lane & 3;
    int warpM = wid & 3, warpN = wid >> 2;
    int e0 = blockIdx.x * 64, n0 = blockIdx.y * 128;

    auto stage = [&](int c) {
        int s = (c - 4) & 1;
        const __half* src = (c < 8) ? g_zmaxh : g_zagrh;
        int kc = (c < 8) ? (c - 4) * 64 : (c - 8) * 64;
        int k0 = c * 64;
        u32 sa = A0 + s * 18432, sb = B0 + s * 9216;
#pragma unroll
        for (int j = 0; j < 4; j++) {
            int f = tid + j * 256;
            int row = f >> 3, kq = f & 7;
            int nr = n0 + row; if (nr >= N) nr = N - 1;
            cpa16(sa + row * 144 + kq * 16, src + (size_t)nr * DDIM + kc + kq * 8);
        }
#pragma unroll
        for (int j = 0; j < 2; j++) {
            int f = tid + j * 256;
            int row = f >> 3, kq = f & 7;
            cpa16(sb + row * 144 + kq * 16, g_wcTh + (size_t)(e0 + row) * 768 + k0 + kq * 8);
        }
    };

    stage(4); CP_COMMIT();

    float d[2][4][4];
#pragma unroll
    for (int mm = 0; mm < 2; mm++)
#pragma unroll
        for (int nn = 0; nn < 4; nn++)
#pragma unroll
            for (int i = 0; i < 4; i++) d[mm][nn][i] = 0.f;

    for (int c = 4; c < 12; c++) {
        int s = (c - 4) & 1;
        CP_WAITALL();
        __syncthreads();
        if (c + 1 < 12) { stage(c + 1); CP_COMMIT(); }

        int abase = s * 4608 + (warpM * 32 + g) * 36;
        int bbase = s * 2304 + (warpN * 32 + g) * 36;
#pragma unroll
        for (int ks = 0; ks < 4; ks++) {
            int ko = ks * 8 + t4;
            u32 a[2][4], b[4][2];
#pragma unroll
            for (int mm = 0; mm < 2; mm++) {
                int ab = abase + mm * 16 * 36 + ko;
                a[mm][0] = Aw[ab];
                a[mm][1] = Aw[ab + 8 * 36];
                a[mm][2] = Aw[ab + 4];
                a[mm][3] = Aw[ab + 8 * 36 + 4];
            }
#pragma unroll
            for (int nn = 0; nn < 4; nn++) {
                int bb_ = bbase + nn * 8 * 36 + ko;
                b[nn][0] = Bw[bb_]; b[nn][1] = Bw[bb_ + 4];
            }
#pragma unroll
            for (int mm = 0; mm < 2; mm++)
#pragma unroll
                for (int nn = 0; nn < 4; nn++)
                    mma16h(d[mm][nn], a[mm], b[nn]);
        }
    }

#pragma unroll
    for (int mm = 0; mm < 2; mm++) {
#pragma unroll
        for (int h = 0; h < 2; h++) {
            int n = n0 + warpM * 32 + mm * 16 + g + h * 8;
            if (n >= N) continue;
#pragma unroll
            for (int nn = 0; nn < 4; nn++) {
                int e = e0 + warpN * 32 + nn * 8 + t4 * 2;
                *(float2*)(g_zpre + (size_t)n * DDIM + e) =
                    make_float2(d[mm][nn][h * 2], d[mm][nn][h * 2 + 1]);
            }
        }
    }
}

// ============================================================================
// Kernel 3b: combine part A — K chunks 0..4 (z_sum fp32, hi/lo split),
// adds g_zpre partial + bias.
// ============================================================================
__global__ void __launch_bounds__(256, 1) k_combine_a(
        const float* __restrict__ bc, int N) {
    extern __shared__ float sh[];
    u32 shb = (u32)__cvta_generic_to_shared(sh);
    float* sAf = sh;                 // 2 x [128][68] fp32
    const u32 A0 = shb, B0 = shb + 2 * 34816;
    const u32* Bw = (const u32*)((const char*)sh + 2 * 34816);

    int tid = threadIdx.x, wid = tid >> 5, lane = tid & 31;
    int g = lane >> 2, t4 = lane & 3;
    int warpM = wid & 3, warpN = wid >> 2;
    int e0 = blockIdx.x * 64, n0 = blockIdx.y * 128;

    auto stage = [&](int c) {
        int k0 = c * 64, s = c & 1;
        u32 sa = A0 + s * 34816, sb = B0 + s * 9216;
#pragma unroll
        for (int j = 0; j < 8; j++) {
            int f = tid + j * 256;
            int row = f >> 4, kq = f & 15;
            int nr = n0 + row; if (nr >= N) nr = N - 1;
            cpa16(sa + row * 272 + kq * 16, g_zsum + (size_t)nr * DDIM + k0 + kq * 4);
        }
#pragma unroll
        for (int j = 0; j < 2; j++) {
            int f = tid + j * 256;
            int row = f >> 3, kq = f & 7;
            cpa16(sb + row * 144 + kq * 16, g_wcTh + (size_t)(e0 + row) * 768 + k0 + kq * 8);
        }
    };

    stage(0); CP_COMMIT();

    float d[2][4][4];
#pragma unroll
    for (int mm = 0; mm < 2; mm++)
#pragma unroll
        for (int nn = 0; nn < 4; nn++)
#pragma unroll
            for (int i = 0; i < 4; i++) d[mm][nn][i] = 0.f;

    for (int c = 0; c < 4; c++) {
        int s = c & 1;
        CP_WAITALL();
        __syncthreads();
        if (c + 1 < 4) { stage(c + 1); CP_COMMIT(); }

        const float* A = sAf + s * 8704 + (warpM * 32 + g) * 68;
        const u32* B = Bw + s * 2304 + (warpN * 32 + g) * 36;
#pragma unroll
        for (int ks = 0; ks < 4; ks++) {
            int kf = ks * 16 + 2 * t4;
            u32 ahi[2][4], alo[2][4], b[4][2];
#pragma unroll
            for (int mm = 0; mm < 2; mm++) {
                const float* ar = A + mm * 16 * 68;
                float2 p0 = *(const float2*)(ar + kf);
                float2 p1 = *(const float2*)(ar + 8 * 68 + kf);
                float2 p2 = *(const float2*)(ar + kf + 8);
                float2 p3 = *(const float2*)(ar + 8 * 68 + kf + 8);
                split2(p0.x, p0.y, ahi[mm][0], alo[mm][0]);
                split2(p1.x, p1.y, ahi[mm][1], alo[mm][1]);
                split2(p2.x, p2.y, ahi[mm][2], alo[mm][2]);
                split2(p3.x, p3.y, ahi[mm][3], alo[mm][3]);
            }
#pragma unroll
            for (int nn = 0; nn < 4; nn++) {
                int bb_ = nn * 8 * 36 + ks * 8 + t4;
                b[nn][0] = B[bb_]; b[nn][1] = B[bb_ + 4];
            }
#pragma unroll
            for (int mm = 0; mm < 2; mm++)
#pragma unroll
                for (int nn = 0; nn < 4; nn++) {
                    mma16h(d[mm][nn], alo[mm], b[nn]);
                    mma16h(d[mm][nn], ahi[mm], b[nn]);
                }
        }
    }

#pragma unroll
    for (int mm = 0; mm < 2; mm++) {
#pragma unroll
        for (int h = 0; h < 2; h++) {
            int n = n0 + warpM * 32 + mm * 16 + g + h * 8;
            if (n >= N) continue;
#pragma unroll
            for (int nn = 0; nn < 4; nn++) {
                int e = e0 + warpN * 32 + nn * 8 + t4 * 2;
                float* po = g_zpre + (size_t)n * DDIM + e;
                float2 prev = *(float2*)po;
                *(float2*)po = make_float2(
                    d[mm][nn][h * 2] + prev.x + __ldg(bc + e),
                    d[mm][nn][h * 2 + 1] + prev.y + __ldg(bc + e + 1));
            }
        }
    }
}

// ============================================================================
// Kernel 4: LayerNorm. One warp per node.
// ============================================================================
__global__ void k_ln(const float* __restrict__ gamma, const float* __restrict__ beta,
                     float* __restrict__ out, int N) {
    int tid = threadIdx.x;
    int lane = tid & 31, wid = tid >> 5;
    int n = blockIdx.x * (blockDim.x >> 5) + wid;
    if (n >= N) return;

    const float* p = g_zpre + (size_t)n * DDIM + lane * 8;
    float4 v0 = *(const float4*)p;
    float4 v1 = *(const float4*)(p + 4);
    float v[8] = {v0.x, v0.y, v0.z, v0.w, v1.x, v1.y, v1.z, v1.w};
    float s = 0.f, q = 0.f;
#pragma unroll
    for (int dd = 0; dd < 8; dd++) { s += v[dd]; q = fmaf(v[dd], v[dd], q); }
#pragma unroll
    for (int off = 16; off > 0; off >>= 1) {
        s += __shfl_xor_sync(0xffffffffu, s, off);
        q += __shfl_xor_sync(0xffffffffu, q, off);
    }
    float mean = s * (1.f / 256.f);
    float var = q * (1.f / 256.f) - mean * mean;
    float inv = rsqrtf(var + 1e-5f);

    const float* gp = gamma + lane * 8;
    const float* bp = beta + lane * 8;
    float4 g0 = *(const float4*)gp, g1 = *(const float4*)(gp + 4);
    float4 b0 = *(const float4*)bp, b1 = *(const float4*)(bp + 4);
    float gg[8] = {g0.x, g0.y, g0.z, g0.w, g1.x, g1.y, g1.z, g1.w};
    float bbv[8] = {b0.x, b0.y, b0.z, b0.w, b1.x, b1.y, b1.z, b1.w};
    float o[8];
#pragma unroll
    for (int dd = 0; dd < 8; dd++) o[dd] = fmaf((v[dd] - mean) * inv, gg[dd], bbv[dd]);

    float* qo = out + (size_t)n * DDIM + lane * 8;
    *(float4*)qo       = make_float4(o[0], o[1], o[2], o[3]);
    *(float4*)(qo + 4) = make_float4(o[4], o[5], o[6], o[7]);
}

// ============================================================================
extern "C" void kernel_launch(void* const* d_in, const int* in_sizes, int n_in,
                              void* d_out, int out_size) {
    const float* zs    = (const float*)d_in[0];
    const float* Wb    = (const float*)d_in[1];
    const float* bb    = (const float*)d_in[2];
    const float* Wmax  = (const float*)d_in[3];
    const float* bmax  = (const float*)d_in[4];
    const float* Wphi  = (const float*)d_in[5];
    const float* bphi  = (const float*)d_in[6];
    const float* Wc    = (const float*)d_in[7];
    const float* bc    = (const float*)d_in[8];
    const float* gamma = (const float*)d_in[9];
    const float* beta  = (const float*)d_in[10];
    float* out = (float*)d_out;

    int N = in_sizes[0] / (MREL * DDIM);
    int nt128 = (N + 127) / 128;
    long long n4 = (long long)in_sizes[0] / 4;

    static cudaStream_t s1 = 0;
    static cudaEvent_t evf = 0, ev1 = 0;
    static int configured = 0;
    if (!configured) {
        cudaFuncSetAttribute(k_gate_logits, cudaFuncAttributeMaxDynamicSharedMemorySize, 71936);
        cudaFuncSetAttribute(k_maxphi_mma, cudaFuncAttributeMaxDynamicSharedMemorySize, 114688);
        cudaFuncSetAttribute(k_combine_b, cudaFuncAttributeMaxDynamicSharedMemorySize, 55296);
        cudaFuncSetAttribute(k_combine_a, cudaFuncAttributeMaxDynamicSharedMemorySize, 88064);
        cudaStreamCreateWithFlags(&s1, cudaStreamNonBlocking);
        cudaEventCreateWithFlags(&evf, cudaEventDisableTiming);
        cudaEventCreateWithFlags(&ev1, cudaEventDisableTiming);
        configured = 1;
    }

    // fork s1 from capture-origin stream (R12-proven topology)
    cudaEventRecord(evf, 0);
    cudaStreamWaitEvent(s1, evf, 0);

    // s1: gate pipeline only (R12-proven)
    k_wbtrans<<<8, 256, 0, s1>>>(Wb);
    k_gate_logits<<<nt128, 256, 71936, s1>>>(zs, bb, N);
    k_gate_zsum2<<<(N + 7) / 8, 256, 0, s1>>>(zs, N);
    cudaEventRecord(ev1, s1);

    // s0: fp16 conversion + weight transposes -> maxphi (R12-proven order)
    k_cvt_zs<<<2048, 256>>>(zs, n4);
    k_wtrans<<<dim3(8, 8, 16), 256>>>(Wmax, Wphi);
    k_wctrans<<<dim3(24, 8), 256>>>(Wc);
    k_maxphi_mma<<<dim3(4, nt128), 256, 114688>>>(bmax, bphi, N);

    // combine part B (z_max/z_agr fp16, single mma)
    k_combine_b<<<dim3(4, nt128), 256, 55296>>>(N);

    // join gate, then combine part A (z_sum hi/lo) + bias finalize
    cudaStreamWaitEvent(0, ev1, 0);
    k_combine_a<<<dim3(4, nt128), 256, 88064>>>(bc, N);

    k_ln<<<(N + 7) / 8, 256>>>(gamma, beta, out, N);
}

// round 16
// speedup vs baseline: 1.3930x; 1.3930x over previous
#include <cuda_runtime.h>
#include <cuda_fp16.h>
#include <math.h>

#define MREL 8
#define DDIM 256
#define MAXN 51200

typedef unsigned int u32;

// ---------------- scratch (no cudaMalloc allowed) ----------------
__device__ __half g_zsh[(size_t)MREL * MAXN * DDIM]; // fp16 copy of zs
__device__ float g_zsum[(size_t)MAXN * DDIM];        // fp32 (precision-critical)
__device__ __half g_zmaxh[(size_t)MAXN * DDIM];      // fp16
__device__ __half g_zagrh[(size_t)MAXN * DDIM];      // fp16
__device__ float g_logits[(size_t)MAXN * MREL];      // fp32
__device__ __half g_wTh[16 * 256 * 256];             // [m*2+mat][e][k] K-major fp16
__device__ __half g_wcTh[256 * 768];                 // [e][k] K-major fp16
__device__ __half g_wbTh[8 * 2048];                  // [j][k] K-major fp16

__device__ __forceinline__ u32 h2u(__half2 h) { return *(u32*)&h; }

// m16n8k16 fp16 mma, fp32 accum
__device__ __forceinline__ void mma16h(float* d, const u32* a, const u32* b) {
    asm volatile(
        "mma.sync.aligned.m16n8k16.row.col.f32.f16.f16.f32 "
        "{%0,%1,%2,%3}, {%4,%5,%6,%7}, {%8,%9}, {%0,%1,%2,%3};"
        : "+f"(d[0]), "+f"(d[1]), "+f"(d[2]), "+f"(d[3])
        : "r"(a[0]), "r"(a[1]), "r"(a[2]), "r"(a[3]), "r"(b[0]), "r"(b[1]));
}
__device__ __forceinline__ void cpa16(u32 dst, const void* src) {
    asm volatile("cp.async.cg.shared.global [%0], [%1], 16;" :: "r"(dst), "l"(src));
}
#define CP_COMMIT()   asm volatile("cp.async.commit_group;")
#define CP_WAIT1()    asm volatile("cp.async.wait_group 1;")
#define CP_WAITALL()  asm volatile("cp.async.wait_group 0;")

// hi/lo fp16 split of a float pair -> two packed b32
__device__ __forceinline__ void split2(float x, float y, u32& hi, u32& lo) {
    __half2 h = __floats2half2_rn(x, y);
    hi = h2u(h);
    __half2 l = __floats2half2_rn(x - __low2float(h), y - __high2float(h));
    lo = h2u(l);
}

// ============================================================================
// zs fp32 -> fp16 copy
// ============================================================================
__global__ void k_cvt_zs(const float* __restrict__ zs, long long n4) {
    long long i = blockIdx.x * (long long)blockDim.x + threadIdx.x;
    long long stride = (long long)gridDim.x * blockDim.x;
    for (; i < n4; i += stride) {
        float4 v = ((const float4*)zs)[i];
        __half2 h0 = __floats2half2_rn(v.x, v.y);
        __half2 h1 = __floats2half2_rn(v.z, v.w);
        ((uint2*)g_zsh)[i] = make_uint2(h2u(h0), h2u(h1));
    }
}

// ============================================================================
// Weight transposes (fp16 outputs, K-major)
// ============================================================================
__global__ void k_wtrans(const float* __restrict__ Wmax, const float* __restrict__ Wphi) {
    __shared__ float t[32][33];
    int z = blockIdx.z;
    const float* src = ((z & 1) ? Wphi : Wmax) + (size_t)(z >> 1) * 65536;
    __half* dst = g_wTh + (size_t)z * 65536;
    int e0 = blockIdx.x * 32, k0 = blockIdx.y * 32;
    int tx = threadIdx.x & 31, ty = threadIdx.x >> 5;
#pragma unroll
    for (int i = 0; i < 4; i++) t[ty + i * 8][tx] = src[(size_t)(k0 + ty + i * 8) * 256 + e0 + tx];
    __syncthreads();
#pragma unroll
    for (int i = 0; i < 4; i++)
        dst[(size_t)(e0 + ty + i * 8) * 256 + k0 + tx] = __float2half_rn(t[tx][ty + i * 8]);
}
__global__ void k_wctrans(const float* __restrict__ Wc) {
    __shared__ float t[32][33];
    int k0 = blockIdx.x * 32, e0 = blockIdx.y * 32;
    int tx = threadIdx.x & 31, ty = threadIdx.x >> 5;
#pragma unroll
    for (int i = 0; i < 4; i++) t[ty + i * 8][tx] = Wc[(size_t)(k0 + ty + i * 8) * 256 + e0 + tx];
    __syncthreads();
#pragma unroll
    for (int i = 0; i < 4; i++)
        g_wcTh[(size_t)(e0 + ty + i * 8) * 768 + k0 + tx] = __float2half_rn(t[tx][ty + i * 8]);
}
__global__ void k_wbtrans(const float* __restrict__ Wb) {
    int k = blockIdx.x * 256 + threadIdx.x;
    if (k < 2048) {
#pragma unroll
        for (int j = 0; j < 8; j++)
            g_wbTh[j * 2048 + k] = __float2half_rn(Wb[k * 8 + j]);
    }
}

// ============================================================================
// Kernel 1a: gate logits GEMM (fp16 mma, A hi/lo split in-register).
// ============================================================================
__global__ void __launch_bounds__(256, 2) k_gate_logits(
        const float* __restrict__ zs, const float* __restrict__ bb, int N) {
    extern __shared__ float sh[];
    u32 shb = (u32)__cvta_generic_to_shared(sh);
    float* sAf = sh;                                  // 2 x [128][68] fp32
    const u32 A0 = shb, B0 = shb + 2 * 34816;
    const u32* Bw = (const u32*)((const char*)sh + 2 * 34816);

    int tid = threadIdx.x, wid = tid >> 5, lane = tid & 31;
    int g = lane >> 2, t4 = lane & 3;
    int n0 = blockIdx.x * 128;

    auto stage = [&](int c) {
        int m = c >> 2, kc = (c & 3) * 64, s = c & 1;
        const float* za = zs + (size_t)m * N * DDIM;
        u32 sa = A0 + s * 34816, sb = B0 + s * 1152;
#pragma unroll
        for (int j = 0; j < 8; j++) {
            int f = tid + j * 256;
            int row = f >> 4, kq = f & 15;
            int nr = n0 + row; if (nr >= N) nr = N - 1;
            cpa16(sa + row * 272 + kq * 16, za + (size_t)nr * DDIM + kc + kq * 4);
        }
        if (tid < 64) {
            int row = tid >> 3, kq = tid & 7;
            cpa16(sb + row * 144 + kq * 16, g_wbTh + (size_t)row * 2048 + c * 64 + kq * 8);
        }
    };

    stage(0); CP_COMMIT();

    float d[4] = {0.f, 0.f, 0.f, 0.f};

    for (int c = 0; c < 32; c++) {
        int s = c & 1;
        CP_WAITALL();
        __syncthreads();
        if (c + 1 < 32) { stage(c + 1); CP_COMMIT(); }

        const float* A = sAf + s * 8704 + (wid * 16 + g) * 68;
        const u32* B = Bw + s * 288 + g * 36;
#pragma unroll
        for (int ks = 0; ks < 4; ks++) {
            int kf = ks * 16 + 2 * t4;
            float2 p0 = *(const float2*)(A + kf);
            float2 p1 = *(const float2*)(A + 8 * 68 + kf);
            float2 p2 = *(const float2*)(A + kf + 8);
            float2 p3 = *(const float2*)(A + 8 * 68 + kf + 8);
            u32 ahi[4], alo[4], b[2];
            split2(p0.x, p0.y, ahi[0], alo[0]);
            split2(p1.x, p1.y, ahi[1], alo[1]);
            split2(p2.x, p2.y, ahi[2], alo[2]);
            split2(p3.x, p3.y, ahi[3], alo[3]);
            b[0] = B[ks * 8 + t4];
            b[1] = B[ks * 8 + t4 + 4];
            mma16h(d, alo, b);
            mma16h(d, ahi, b);
        }
    }

    float bb0 = __ldg(bb + t4 * 2), bb1 = __ldg(bb + t4 * 2 + 1);
#pragma unroll
    for (int h = 0; h < 2; h++) {
        int n = n0 + wid * 16 + g + h * 8;
        if (n < N)
            *(float2*)(g_logits + (size_t)n * 8 + t4 * 2) =
                make_float2(d[h * 2] + bb0, d[h * 2 + 1] + bb1);
    }
}

// ============================================================================
// Kernel 1b: streaming softmax + z_sum (fp32 zs, exact). One warp per node.
// ============================================================================
__global__ void k_gate_zsum2(const float* __restrict__ zs, int N) {
    int tid = threadIdx.x;
    int lane = tid & 31, wid = tid >> 5;
    int n = blockIdx.x * 8 + wid;
    if (n >= N) return;

    const float* L = g_logits + (size_t)n * 8;
    float lg[8];
#pragma unroll
    for (int j = 0; j < 8; j++) lg[j] = __ldg(L + j);
    float mx = -1e30f;
#pragma unroll
    for (int j = 0; j < 8; j++) mx = fmaxf(mx, lg[j]);
    float gsm[8], se = 0.f;
#pragma unroll
    for (int j = 0; j < 8; j++) { gsm[j] = expf(lg[j] - mx); se += gsm[j]; }
    float inv = 1.f / se;
#pragma unroll
    for (int j = 0; j < 8; j++) gsm[j] *= inv;

    const float* base = zs + (size_t)n * DDIM + lane;
    float* q = g_zsum + (size_t)n * DDIM + lane;
    size_t mstr = (size_t)N * DDIM;
#pragma unroll
    for (int i = 0; i < 8; i++) {
        float v[8];
#pragma unroll
        for (int m = 0; m < 8; m++) v[m] = __ldg(base + m * mstr + 32 * i);
        float a = 0.f;
#pragma unroll
        for (int m = 0; m < 8; m++) a = fmaf(gsm[m], v[m], a);
        q[32 * i] = a;
    }
}

// ============================================================================
// Kernel 2: fused dual-GEMM + fold, fp16 m16n8k16. fp16 z_max / z_agr out.
// CTA 128 x 64, K-chunk 64, 3-stage cp.async distance 2.
// ============================================================================
__global__ void __launch_bounds__(256, 1) k_maxphi_mma(
        const float* __restrict__ bmax, const float* __restrict__ bphi, int N) {
    extern __shared__ float sh[];
    u32 shb = (u32)__cvta_generic_to_shared(sh);
    float* sbm = sh;                    // [8][64]
    float* sbp = sh + 512;              // [8][64]
    const u32 A0 = shb + 4096, B0 = shb + 4096 + 3 * 18432;
    const u32* Aw = (const u32*)((const char*)sh + 4096);
    const u32* Bw = (const u32*)((const char*)sh + 4096 + 3 * 18432);

    int tid = threadIdx.x, wid = tid >> 5, lane = tid & 31;
    int g = lane >> 2, t4 = lane & 3;
    int warpM = wid & 3, warpN = wid >> 2;
    int e0 = blockIdx.x * 64, n0 = blockIdx.y * 128;

    for (int i = tid; i < MREL * 64; i += 256) {
        int m = i >> 6, c = i & 63;
        sbm[i] = bmax[m * DDIM + e0 + c];
        sbp[i] = bphi[m * DDIM + e0 + c];
    }

    auto stage = [&](int it) {
        int m = it >> 2, k0 = (it & 3) * 64, s = it % 3;
        const __half* za = g_zsh + (size_t)m * N * DDIM;
        const __half* wb = g_wTh + (size_t)m * 2 * 65536;
        u32 sa = A0 + s * 18432, sb = B0 + s * 18432;
#pragma unroll
        for (int j = 0; j < 4; j++) {
            int f = tid + j * 256;
            int row = f >> 3, kq = f & 7;
            int nr = n0 + row; if (nr >= N) nr = N - 1;
            cpa16(sa + row * 144 + kq * 16, za + (size_t)nr * DDIM + k0 + kq * 8);
        }
#pragma unroll
        for (int j = 0; j < 4; j++) {
            int f = tid + j * 256;
            int row = f >> 3, kq = f & 7;
            const __half* src = wb + (row >= 64 ? 65536 : 0)
                                + (size_t)(e0 + (row & 63)) * 256 + k0 + kq * 8;
            cpa16(sb + row * 144 + kq * 16, src);
        }
    };

    stage(0); CP_COMMIT();
    stage(1); CP_COMMIT();

    float stP[32], stF1[32], stF2[32];
#pragma unroll
    for (int i = 0; i < 32; i++) { stP[i] = -3.0e38f; stF1[i] = 0.f; stF2[i] = 0.f; }

    float dP[2][4][4], dF[2][4][4];

    for (int it = 0; it < 32; it++) {
        int m = it >> 2, chunk = it & 3, s = it % 3;
        if (chunk == 0) {
#pragma unroll
            for (int mm = 0; mm < 2; mm++)
#pragma unroll
                for (int nn = 0; nn < 4; nn++)
#pragma unroll
                    for (int i = 0; i < 4; i++) { dP[mm][nn][i] = 0.f; dF[mm][nn][i] = 0.f; }
        }
        CP_WAIT1();
        __syncthreads();
        if (it + 2 < 32) { stage(it + 2); CP_COMMIT(); }

        int abase = s * 4608 + (warpM * 32 + g) * 36;
        int bbase = s * 4608 + (warpN * 32 + g) * 36;
#pragma unroll
        for (int ks = 0; ks < 4; ks++) {
            int ko = ks * 8 + t4;
            u32 a[2][4], bp[4][2], bf[4][2];
#pragma unroll
            for (int mm = 0; mm < 2; mm++) {
                int ab = abase + mm * 16 * 36 + ko;
                a[mm][0] = Aw[ab];
                a[mm][1] = Aw[ab + 8 * 36];
                a[mm][2] = Aw[ab + 4];
                a[mm][3] = Aw[ab + 8 * 36 + 4];
            }
#pragma unroll
            for (int nn = 0; nn < 4; nn++) {
                int bb_ = bbase + nn * 8 * 36 + ko;
                bp[nn][0] = Bw[bb_];           bp[nn][1] = Bw[bb_ + 4];
                bf[nn][0] = Bw[bb_ + 64 * 36]; bf[nn][1] = Bw[bb_ + 64 * 36 + 4];
            }
#pragma unroll
            for (int mm = 0; mm < 2; mm++)
#pragma unroll
                for (int nn = 0; nn < 4; nn++) {
                    mma16h(dP[mm][nn], a[mm], bp[nn]);
                    mma16h(dF[mm][nn], a[mm], bf[nn]);
                }
        }

        if (chunk == 3) {
#pragma unroll
            for (int nn = 0; nn < 4; nn++) {
                int cb = m * 64 + warpN * 32 + nn * 8 + t4 * 2;
                float bm0 = sbm[cb], bm1 = sbm[cb + 1];
                float bp0 = sbp[cb], bp1 = sbp[cb + 1];
#pragma unroll
                for (int mm = 0; mm < 2; mm++) {
                    int ix = mm * 16 + nn * 4;
                    stP[ix + 0] = fmaxf(stP[ix + 0], dP[mm][nn][0] + bm0);
                    stP[ix + 1] = fmaxf(stP[ix + 1], dP[mm][nn][1] + bm1);
                    stP[ix + 2] = fmaxf(stP[ix + 2], dP[mm][nn][2] + bm0);
                    stP[ix + 3] = fmaxf(stP[ix + 3], dP[mm][nn][3] + bm1);
                    float v0 = dF[mm][nn][0] + bp0, v1 = dF[mm][nn][1] + bp1;
                    float v2 = dF[mm][nn][2] + bp0, v3 = dF[mm][nn][3] + bp1;
                    stF1[ix + 0] += v0; stF2[ix + 0] = fmaf(v0, v0, stF2[ix + 0]);
                    stF1[ix + 1] += v1; stF2[ix + 1] = fmaf(v1, v1, stF2[ix + 1]);
                    stF1[ix + 2] += v2; stF2[ix + 2] = fmaf(v2, v2, stF2[ix + 2]);
                    stF1[ix + 3] += v3; stF2[ix + 3] = fmaf(v3, v3, stF2[ix + 3]);
                }
            }
        }
    }

#pragma unroll
    for (int mm = 0; mm < 2; mm++) {
#pragma unroll
        for (int h = 0; h < 2; h++) {
            int n = n0 + warpM * 32 + mm * 16 + g + h * 8;
            if (n >= N) continue;
#pragma unroll
            for (int nn = 0; nn < 4; nn++) {
                int ix = mm * 16 + nn * 4 + h * 2;
                int e = e0 + warpN * 32 + nn * 8 + t4 * 2;
                *(u32*)(g_zmaxh + (size_t)n * DDIM + e) =
                    h2u(__floats2half2_rn(stP[ix], stP[ix + 1]));
                float a0 = 0.5f * (stF1[ix] * stF1[ix] - stF2[ix]);
                float a1 = 0.5f * (stF1[ix + 1] * stF1[ix + 1] - stF2[ix + 1]);
                *(u32*)(g_zagrh + (size_t)n * DDIM + e) =
                    h2u(__floats2half2_rn(a0, a1));
            }
        }
    }
}

// ============================================================================
// Kernel 3: merged combine GEMM + LayerNorm. CTA = 64 nodes x FULL 256 e.
// 8 warps: warpM = wid&1 (32 rows), warpN = wid>>1 (64 e-cols).
// Chunks: idx 0..7 -> K chunks 4..11 (zmaxh/zagrh fp16, single mma);
//         idx 8..11 -> K chunks 0..3 (zsum fp32, hi/lo split, 2 mma).
// Epilogue: + bias, in-CTA LN (quad shfl + smem cross-warpN), write out.
// smem: bc/gamma/beta 3x256 f | LN 512 f | A 2 x 17408 B | B 2 x 36864 B
//     = 5120 + 34816 + 73728 = 113664 B. 1 CTA/SM.
// ============================================================================
__global__ void __launch_bounds__(256, 1) k_combine_ln(
        const float* __restrict__ bc, const float* __restrict__ gamma,
        const float* __restrict__ beta, float* __restrict__ out, int N) {
    extern __shared__ float sh[];
    u32 shb = (u32)__cvta_generic_to_shared(sh);
    float* bcs = sh;           // [256]
    float* gms = sh + 256;     // [256]
    float* bts = sh + 512;     // [256]
    float* lns = sh + 768;     // [2][64][4]
    float* Af  = sh + 1280;    // A stages (fp32 view)
    const u32 A0 = shb + 5120, B0 = shb + 5120 + 2 * 17408;
    const u32* Aw = (const u32*)(sh + 1280);
    const u32* Bw = (const u32*)((const char*)sh + 5120 + 2 * 17408);

    int tid = threadIdx.x, wid = tid >> 5, lane = tid & 31;
    int g = lane >> 2, t4 = lane & 3;
    int warpM = wid & 1, warpN = wid >> 1;
    int n0 = blockIdx.x * 64;

    bcs[tid] = __ldg(bc + tid);
    gms[tid] = __ldg(gamma + tid);
    bts[tid] = __ldg(beta + tid);

    auto stage = [&](int idx) {
        int s = idx & 1;
        int c = (idx < 8) ? idx + 4 : idx - 8;
        int k0 = c * 64;
        u32 sa = A0 + s * 17408, sb = B0 + s * 36864;
#pragma unroll
        for (int j = 0; j < 8; j++) {                  // B: 2048 16B chunks (256 e-rows)
            int f = tid + j * 256;
            int row = f >> 3, kq = f & 7;
            cpa16(sb + row * 144 + kq * 16, g_wcTh + (size_t)row * 768 + k0 + kq * 8);
        }
        if (idx < 8) {                                 // A fp16: 512 chunks (64 rows x 8)
            const __half* src = (c < 8) ? g_zmaxh : g_zagrh;
            int kc = (c < 8) ? (c - 4) * 64 : (c - 8) * 64;
#pragma unroll
            for (int j = 0; j < 2; j++) {
                int f = tid + j * 256;
                int row = f >> 3, kq = f & 7;
                int nr = n0 + row; if (nr >= N) nr = N - 1;
                cpa16(sa + row * 144 + kq * 16, src + (size_t)nr * DDIM + kc + kq * 8);
            }
        } else {                                       // A fp32: 1024 chunks (64 rows x 16)
#pragma unroll
            for (int j = 0; j < 4; j++) {
                int f = tid + j * 256;
                int row = f >> 4, kq = f & 15;
                int nr = n0 + row; if (nr >= N) nr = N - 1;
                cpa16(sa + row * 272 + kq * 16, g_zsum + (size_t)nr * DDIM + k0 + kq * 4);
            }
        }
    };

    stage(0); CP_COMMIT();

    float d[2][8][4];
#pragma unroll
    for (int mm = 0; mm < 2; mm++)
#pragma unroll
        for (int nn = 0; nn < 8; nn++)
#pragma unroll
            for (int i = 0; i < 4; i++) d[mm][nn][i] = 0.f;

    for (int idx = 0; idx < 12; idx++) {
        int s = idx & 1;
        CP_WAITALL();
        __syncthreads();
        if (idx + 1 < 12) { stage(idx + 1); CP_COMMIT(); }

        int bbase = s * 9216 + (warpN * 64 + g) * 36;
        if (idx < 8) {
            int abase = s * 4352 + (warpM * 32 + g) * 36;
#pragma unroll
            for (int ks = 0; ks < 4; ks++) {
                int ko = ks * 8 + t4;
                u32 a[2][4], b[8][2];
#pragma unroll
                for (int mm = 0; mm < 2; mm++) {
                    int ab = abase + mm * 16 * 36 + ko;
                    a[mm][0] = Aw[ab];
                    a[mm][1] = Aw[ab + 8 * 36];
                    a[mm][2] = Aw[ab + 4];
                    a[mm][3] = Aw[ab + 8 * 36 + 4];
                }
#pragma unroll
                for (int nn = 0; nn < 8; nn++) {
                    int bb_ = bbase + nn * 8 * 36 + ko;
                    b[nn][0] = Bw[bb_]; b[nn][1] = Bw[bb_ + 4];
                }
#pragma unroll
                for (int mm = 0; mm < 2; mm++)
#pragma unroll
                    for (int nn = 0; nn < 8; nn++)
                        mma16h(d[mm][nn], a[mm], b[nn]);
            }
        } else {
            const float* A = Af + s * 4352 + (warpM * 32 + g) * 68;
#pragma unroll
            for (int ks = 0; ks < 4; ks++) {
                int kf = ks * 16 + 2 * t4;
                u32 ahi[2][4], alo[2][4], b[8][2];
#pragma unroll
                for (int mm = 0; mm < 2; mm++) {
                    const float* ar = A + mm * 16 * 68;
                    float2 p0 = *(const float2*)(ar + kf);
                    float2 p1 = *(const float2*)(ar + 8 * 68 + kf);
                    float2 p2 = *(const float2*)(ar + kf + 8);
                    float2 p3 = *(const float2*)(ar + 8 * 68 + kf + 8);
                    split2(p0.x, p0.y, ahi[mm][0], alo[mm][0]);
                    split2(p1.x, p1.y, ahi[mm][1], alo[mm][1]);
                    split2(p2.x, p2.y, ahi[mm][2], alo[mm][2]);
                    split2(p3.x, p3.y, ahi[mm][3], alo[mm][3]);
                }
#pragma unroll
                for (int nn = 0; nn < 8; nn++) {
                    int bb_ = bbase + nn * 8 * 36 + ks * 8 + t4;
                    b[nn][0] = Bw[bb_]; b[nn][1] = Bw[bb_ + 4];
                }
#pragma unroll
                for (int mm = 0; mm < 2; mm++)
#pragma unroll
                    for (int nn = 0; nn < 8; nn++) {
                        mma16h(d[mm][nn], alo[mm], b[nn]);
                        mma16h(d[mm][nn], ahi[mm], b[nn]);
                    }
            }
        }
    }

    // ---- epilogue: + bias, LN stats ----
    float vs[2][2], vq[2][2];
#pragma unroll
    for (int mm = 0; mm < 2; mm++)
#pragma unroll
        for (int h = 0; h < 2; h++) { vs[mm][h] = 0.f; vq[mm][h] = 0.f; }

#pragma unroll
    for (int nn = 0; nn < 8; nn++) {
        int e = warpN * 64 + nn * 8 + t4 * 2;
        float b0 = bcs[e], b1 = bcs[e + 1];
#pragma unroll
        for (int mm = 0; mm < 2; mm++) {
            d[mm][nn][0] += b0; d[mm][nn][1] += b1;
            d[mm][nn][2] += b0; d[mm][nn][3] += b1;
            vs[mm][0] += d[mm][nn][0] + d[mm][nn][1];
            vq[mm][0] = fmaf(d[mm][nn][0], d[mm][nn][0], fmaf(d[mm][nn][1], d[mm][nn][1], vq[mm][0]));
            vs[mm][1] += d[mm][nn][2] + d[mm][nn][3];
            vq[mm][1] = fmaf(d[mm][nn][2], d[mm][nn][2], fmaf(d[mm][nn][3], d[mm][nn][3], vq[mm][1]));
        }
    }
    // reduce across the 4 t4 lanes of the quad (same g)
#pragma unroll
    for (int mm = 0; mm < 2; mm++)
#pragma unroll
        for (int h = 0; h < 2; h++) {
            vs[mm][h] += __shfl_xor_sync(0xffffffffu, vs[mm][h], 1);
            vs[mm][h] += __shfl_xor_sync(0xffffffffu, vs[mm][h], 2);
            vq[mm][h] += __shfl_xor_sync(0xffffffffu, vq[mm][h], 1);
            vq[mm][h] += __shfl_xor_sync(0xffffffffu, vq[mm][h], 2);
        }
    if (t4 == 0) {
#pragma unroll
        for (int mm = 0; mm < 2; mm++)
#pragma unroll
            for (int h = 0; h < 2; h++) {
                int rl = warpM * 32 + mm * 16 + h * 8 + g;
                lns[rl * 4 + warpN] = vs[mm][h];
                lns[256 + rl * 4 + warpN] = vq[mm][h];
            }
    }
    __syncthreads();

#pragma unroll
    for (int mm = 0; mm < 2; mm++) {
#pragma unroll
        for (int h = 0; h < 2; h++) {
            int rl = warpM * 32 + mm * 16 + h * 8 + g;
            float ts = lns[rl * 4] + lns[rl * 4 + 1] + lns[rl * 4 + 2] + lns[rl * 4 + 3];
            float tq = lns[256 + rl * 4] + lns[256 + rl * 4 + 1]
                     + lns[256 + rl * 4 + 2] + lns[256 + rl * 4 + 3];
            float mean = ts * (1.f / 256.f);
            float var = tq * (1.f / 256.f) - mean * mean;
            float inv = rsqrtf(var + 1e-5f);
            int n = n0 + rl;
            if (n < N) {
#pragma unroll
                for (int nn = 0; nn < 8; nn++) {
                    int e = warpN * 64 + nn * 8 + t4 * 2;
                    float o0 = fmaf((d[mm][nn][h * 2] - mean) * inv, gms[e], bts[e]);
                    float o1 = fmaf((d[mm][nn][h * 2 + 1] - mean) * inv, gms[e + 1], bts[e + 1]);
                    *(float2*)(out + (size_t)n * DDIM + e) = make_float2(o0, o1);
                }
            }
        }
    }
}

// ============================================================================
extern "C" void kernel_launch(void* const* d_in, const int* in_sizes, int n_in,
                              void* d_out, int out_size) {
    const float* zs    = (const float*)d_in[0];
    const float* Wb    = (const float*)d_in[1];
    const float* bb    = (const float*)d_in[2];
    const float* Wmax  = (const float*)d_in[3];
    const float* bmax  = (const float*)d_in[4];
    const float* Wphi  = (const float*)d_in[5];
    const float* bphi  = (const float*)d_in[6];
    const float* Wc    = (const float*)d_in[7];
    const float* bc    = (const float*)d_in[8];
    const float* gamma = (const float*)d_in[9];
    const float* beta  = (const float*)d_in[10];
    float* out = (float*)d_out;

    int N = in_sizes[0] / (MREL * DDIM);
    int nt128 = (N + 127) / 128;
    int nt64  = (N + 63) / 64;
    long long n4 = (long long)in_sizes[0] / 4;

    static cudaStream_t s1 = 0;
    static cudaEvent_t evf = 0, ev1 = 0;
    static int configured = 0;
    if (!configured) {
        cudaFuncSetAttribute(k_gate_logits, cudaFuncAttributeMaxDynamicSharedMemorySize, 71936);
        cudaFuncSetAttribute(k_maxphi_mma, cudaFuncAttributeMaxDynamicSharedMemorySize, 114688);
        cudaFuncSetAttribute(k_combine_ln, cudaFuncAttributeMaxDynamicSharedMemorySize, 113664);
        cudaStreamCreateWithFlags(&s1, cudaStreamNonBlocking);
        cudaEventCreateWithFlags(&evf, cudaEventDisableTiming);
        cudaEventCreateWithFlags(&ev1, cudaEventDisableTiming);
        configured = 1;
    }

    // fork s1 from capture-origin stream (R12/R15-proven topology)
    cudaEventRecord(evf, 0);
    cudaStreamWaitEvent(s1, evf, 0);

    // s1: gate pipeline only
    k_wbtrans<<<8, 256, 0, s1>>>(Wb);
    k_gate_logits<<<nt128, 256, 71936, s1>>>(zs, bb, N);
    k_gate_zsum2<<<(N + 7) / 8, 256, 0, s1>>>(zs, N);
    cudaEventRecord(ev1, s1);

    // s0: fp16 conversion + weight transposes -> maxphi
    k_cvt_zs<<<2048, 256>>>(zs, n4);
    k_wtrans<<<dim3(8, 8, 16), 256>>>(Wmax, Wphi);
    k_wctrans<<<dim3(24, 8), 256>>>(Wc);
    k_maxphi_mma<<<dim3(4, nt128), 256, 114688>>>(bmax, bphi, N);

    // join gate, then merged combine + LayerNorm (writes out directly)
    cudaStreamWaitEvent(0, ev1, 0);
    k_combine_ln<<<nt64, 256, 113664>>>(bc, gamma, beta, out, N);
}